// round 1
// baseline (speedup 1.0000x reference)
#include <cuda_runtime.h>

// Problem constants (from reference):
//   B=64, S=128, T=16, VOCAB=50000, ENT_VOCAB=400000, E_ELMO=1024, D_TRI=100
// Inputs (metadata order):
//   d_in[0] inputs          int32  [B,S]            = 8192
//   d_in[1] triples         int32  [B,S,T,3]        = 393216
//   d_in[2] id2_ids_batch   int32  [B,S,T]          = 131072
//   d_in[3] embedding_table f32    [VOCAB, 1024]    = 51200000
//   d_in[4] entity_table    f32    [ENT_VOCAB, 100] = 40000000
// Output: f32 [B,S,1124] = 9207808

#define NB 64
#define NS 128
#define NT 16
#define NE 1024
#define ND 100
#define OUTW (NE + ND)   // 1124
#define NTOK (NB * NS)   // 8192

__global__ __launch_bounds__(256, 8)
void triple_fuse_kernel(const int* __restrict__ inputs,
                        const int* __restrict__ triples,
                        const int* __restrict__ id2,
                        const float* __restrict__ emb,
                        const float* __restrict__ ent,
                        float* __restrict__ out)
{
    const int token = blockIdx.x;      // 0 .. NTOK-1
    const int tid   = threadIdx.x;     // 0 .. 255

    __shared__ int   s_idx[NT];
    __shared__ int   s_val[NT];
    __shared__ float s_inv;            // 1/cnt, or 0 if cnt==0

    // --- decode triple slots into shared ---
    if (tid < NT) {
        const int flag = id2[token * NT + tid];
        const int* tr  = triples + ((size_t)(token * NT + tid)) * 3;
        const int head = tr[0];
        const int tail = tr[1];
        const int v    = (flag == 1) | (flag == 2);
        s_val[tid] = v;
        s_idx[tid] = (flag == 1) ? tail : head;
    }
    // token-embedding row index (read by all threads; broadcast from L1)
    const int row = inputs[token];

    __syncthreads();

    if (tid == 0) {
        int c = 0;
        #pragma unroll
        for (int j = 0; j < NT; ++j) c += s_val[j];
        s_inv = (c > 0) ? (1.0f / (float)c) : 0.0f;
    }

    // --- token embedding copy: 256 threads x float4 = 1024 floats ---
    // out row base: token*1124 floats = token*4496 bytes, 16B aligned.
    const float4* __restrict__ src = (const float4*)(emb + (size_t)row * NE);
    float4* __restrict__ dst       = (float4*)(out + (size_t)token * OUTW);
    dst[tid] = src[tid];

    __syncthreads();

    // --- entity average: threads 0..99, one output dim each ---
    if (tid < ND) {
        float sum = 0.0f;
        #pragma unroll
        for (int j = 0; j < NT; ++j) {
            if (s_val[j]) {
                sum += ent[(size_t)s_idx[j] * ND + tid];
            }
        }
        out[(size_t)token * OUTW + NE + tid] = sum * s_inv;
    }
}

extern "C" void kernel_launch(void* const* d_in, const int* in_sizes, int n_in,
                              void* d_out, int out_size)
{
    const int*   inputs  = (const int*)d_in[0];
    const int*   triples = (const int*)d_in[1];
    const int*   id2     = (const int*)d_in[2];
    const float* emb     = (const float*)d_in[3];
    const float* ent     = (const float*)d_in[4];
    float*       out     = (float*)d_out;

    triple_fuse_kernel<<<NTOK, 256>>>(inputs, triples, id2, emb, ent, out);
}

// round 4
// speedup vs baseline: 1.8112x; 1.8112x over previous
#include <cuda_runtime.h>

// Problem constants:
//   B=64, S=128, T=16, VOCAB=50000, ENT_VOCAB=400000, E_ELMO=1024, D_TRI=100
// Inputs (metadata order):
//   d_in[0] inputs          int32  [B,S]            = 8192
//   d_in[1] triples         int32  [B,S,T,3]        = 393216
//   d_in[2] id2_ids_batch   int32  [B,S,T]          = 131072
//   d_in[3] embedding_table f32    [VOCAB, 1024]
//   d_in[4] entity_table    f32    [ENT_VOCAB, 100]
// Output: f32 [B,S,1124]

#define NT 16
#define NE 1024
#define ND 100
#define OUTW (NE + ND)   // 1124
#define NTOK (64 * 128)  // 8192

__global__ __launch_bounds__(256, 8)
void triple_fuse_warp_kernel(const int* __restrict__ inputs,
                             const int* __restrict__ triples,
                             const int* __restrict__ id2,
                             const float* __restrict__ emb,
                             const float* __restrict__ ent,
                             float* __restrict__ out)
{
    const int warp  = (blockIdx.x * blockDim.x + threadIdx.x) >> 5; // token id
    const int lane  = threadIdx.x & 31;
    // grid is exact: 1024 blocks * 8 warps = 8192 tokens

    // --- decode triple slots (lanes 0..15) ---
    int  eidx = 0;
    bool v    = false;
    if (lane < NT) {
        const int  flag = id2[warp * NT + lane];
        const int* tr   = triples + ((size_t)(warp * NT + lane)) * 3;
        const int  head = tr[0];
        const int  tail = tr[1];
        v    = (flag == 1) | (flag == 2);
        eidx = (flag == 1) ? tail : head;
    }
    const unsigned vb = __ballot_sync(0xffffffffu, v);   // bits 0..15

    // token embedding row (same address across warp -> one broadcast load)
    const int row = inputs[warp];

    // --- token embedding copy: 32 lanes x 8 float4 = 1024 floats ---
    // Streaming hints: no reuse on this 33MB/37MB path; keep L2 for gathers.
    const float4* __restrict__ src = (const float4*)(emb + (size_t)row * NE);
    float4* __restrict__ dst       = (float4*)(out + (size_t)warp * OUTW);
    #pragma unroll
    for (int i = 0; i < 8; ++i) {
        float4 t = __ldcs(&src[lane + 32 * i]);
        __stcs(&dst[lane + 32 * i], t);
    }

    // --- entity average: 25 lanes x float4 (= 100 dims) ---
    const int   cnt = __popc(vb);
    const float inv = cnt ? (1.0f / (float)cnt) : 0.0f;

    float4 acc = make_float4(0.f, 0.f, 0.f, 0.f);
    #pragma unroll
    for (int j = 0; j < NT; ++j) {
        const int ej = __shfl_sync(0xffffffffu, eidx, j);
        if (((vb >> j) & 1u) && lane < 25) {
            const float4 e = *(const float4*)(ent + (size_t)ej * ND + lane * 4);
            acc.x += e.x; acc.y += e.y; acc.z += e.z; acc.w += e.w;
        }
    }
    if (lane < 25) {
        float4 r = make_float4(acc.x * inv, acc.y * inv, acc.z * inv, acc.w * inv);
        __stcs((float4*)(out + (size_t)warp * OUTW + NE + lane * 4), r);
    }
}

extern "C" void kernel_launch(void* const* d_in, const int* in_sizes, int n_in,
                              void* d_out, int out_size)
{
    const int*   inputs  = (const int*)d_in[0];
    const int*   triples = (const int*)d_in[1];
    const int*   id2     = (const int*)d_in[2];
    const float* emb     = (const float*)d_in[3];
    const float* ent     = (const float*)d_in[4];
    float*       out     = (float*)d_out;

    triple_fuse_warp_kernel<<<NTOK / 8, 256>>>(inputs, triples, id2, emb, ent, out);
}